// round 3
// baseline (speedup 1.0000x reference)
#include <cuda_runtime.h>

typedef unsigned long long ull;

#define THREADS 256
#define BM 128
#define BK 32
#define BU 32
#define AP (BM + 4)   // As row pad
#define BP3 100       // Bs pad for 96 cols (3 gates)
#define BP2 68        // Bs pad for 64 cols (2 gates)

#define DH 256
#define NLEAF 16384
#define DIN 300

// ---------- packed fp32x2 helpers (sm_103a FFMA2 path, PTX-only) ----------
__device__ __forceinline__ ull pack2(float x) {
    ull r; asm("mov.b64 %0, {%1, %1};" : "=l"(r) : "f"(x)); return r;
}
__device__ __forceinline__ float2 unpack2(ull v) {
    float2 r; asm("mov.b64 {%0, %1}, %2;" : "=f"(r.x), "=f"(r.y) : "l"(v)); return r;
}
__device__ __forceinline__ void ffma2(ull& d, ull a, ull b) {
    asm("fma.rn.f32x2 %0, %1, %2, %0;" : "+l"(d) : "l"(a), "l"(b));
}
__device__ __forceinline__ float sigf(float x) { return 1.0f / (1.0f + expf(-x)); }

// ---------- scratch (device globals: no allocation allowed) ----------
__device__ float g_hA[NLEAF * DH];
__device__ float g_cA[NLEAF * DH];
__device__ float g_hB[(NLEAF / 2) * DH];
__device__ float g_cB[(NLEAF / 2) * DH];
__device__ float g_hl[(NLEAF / 2) * DH];
__device__ float g_cl[(NLEAF / 2) * DH];
__device__ float g_rc[DH];   // root cell (unused output)

// =====================================================================
// Leaf: gx = emb[ids] @ Wx + bx ; gi,go,cpre = split(gx)
// c = sig(gi)*tanh(cpre) ; h = sig(go)*tanh(c)
// Block: 128 leaves x 32 hidden units (x3 gate cols). Thread: 8 rows x 6 cols.
// =====================================================================
__global__ void __launch_bounds__(THREADS, 2)
leaf_kernel(const int* __restrict__ ids, const float* __restrict__ emb,
            const float* __restrict__ Wx, const float* __restrict__ bx)
{
    __shared__ float As[BK][AP];
    __shared__ float Bs[BK][BP3];
    __shared__ int rid[BM];

    const int tid = threadIdx.x;
    const int tx = tid & 15;
    const int ty = tid >> 4;
    const int m0 = blockIdx.x * BM;
    const int u0 = blockIdx.y * BU;

    if (tid < BM) rid[tid] = ids[m0 + tid];
    __syncthreads();

    ull acc[8][3];
#pragma unroll
    for (int r = 0; r < 8; r++)
#pragma unroll
        for (int g = 0; g < 3; g++) acc[r][g] = 0ull;

    for (int k0 = 0; k0 < DIN; k0 += BK) {
        const int klim = DIN - k0;   // >= BK except last chunk (12)
        // ---- stage A: 4 float4 per thread, transpose into As[k][m] ----
#pragma unroll
        for (int i = 0; i < 4; i++) {
            int idx = tid + i * THREADS;
            int m = idx >> 3;
            int kq = idx & 7;
            float4 v = make_float4(0.f, 0.f, 0.f, 0.f);
            if (kq * 4 < klim)
                v = *reinterpret_cast<const float4*>(&emb[(size_t)rid[m] * DIN + k0 + kq * 4]);
            As[kq * 4 + 0][m] = v.x;
            As[kq * 4 + 1][m] = v.y;
            As[kq * 4 + 2][m] = v.z;
            As[kq * 4 + 3][m] = v.w;
        }
        // ---- stage B: 3 float4 per thread ----
        {
            int kk = tid >> 3;
#pragma unroll
            for (int i = 0; i < 3; i++) {
                int c4 = (tid & 7) + i * 8;
                int g = c4 >> 3;
                int u4 = c4 & 7;
                float4 w = make_float4(0.f, 0.f, 0.f, 0.f);
                if (kk < klim)
                    w = *reinterpret_cast<const float4*>(
                        &Wx[(size_t)(k0 + kk) * 768 + g * 256 + u0 + u4 * 4]);
                *reinterpret_cast<float4*>(&Bs[kk][g * 32 + u4 * 4]) = w;
            }
        }
        __syncthreads();
#pragma unroll 8
        for (int kk = 0; kk < BK; kk++) {
            float4 a0 = *reinterpret_cast<const float4*>(&As[kk][ty * 8]);
            float4 a1 = *reinterpret_cast<const float4*>(&As[kk][ty * 8 + 4]);
            ull ap[8] = {pack2(a0.x), pack2(a0.y), pack2(a0.z), pack2(a0.w),
                         pack2(a1.x), pack2(a1.y), pack2(a1.z), pack2(a1.w)};
            ull b0 = *reinterpret_cast<const ull*>(&Bs[kk][tx * 2]);
            ull b1 = *reinterpret_cast<const ull*>(&Bs[kk][32 + tx * 2]);
            ull b2 = *reinterpret_cast<const ull*>(&Bs[kk][64 + tx * 2]);
#pragma unroll
            for (int r = 0; r < 8; r++) {
                ffma2(acc[r][0], ap[r], b0);
                ffma2(acc[r][1], ap[r], b1);
                ffma2(acc[r][2], ap[r], b2);
            }
        }
        __syncthreads();
    }

    const int u = u0 + tx * 2;
    const float2 bgi = make_float2(bx[u],       bx[u + 1]);
    const float2 bgo = make_float2(bx[256 + u], bx[256 + u + 1]);
    const float2 bcp = make_float2(bx[512 + u], bx[512 + u + 1]);
#pragma unroll
    for (int r = 0; r < 8; r++) {
        int row = m0 + ty * 8 + r;
        float2 gi = unpack2(acc[r][0]); gi.x += bgi.x; gi.y += bgi.y;
        float2 go = unpack2(acc[r][1]); go.x += bgo.x; go.y += bgo.y;
        float2 cp = unpack2(acc[r][2]); cp.x += bcp.x; cp.y += bcp.y;
        float cx = sigf(gi.x) * tanhf(cp.x);
        float cy = sigf(gi.y) * tanhf(cp.y);
        float hx = sigf(go.x) * tanhf(cx);
        float hy = sigf(go.y) * tanhf(cy);
        *reinterpret_cast<float2*>(&g_cA[(size_t)row * DH + u]) = make_float2(cx, cy);
        *reinterpret_cast<float2*>(&g_hA[(size_t)row * DH + u]) = make_float2(hx, hy);
    }
}

// =====================================================================
// Stage 1 per level: left child (sibling = None).
// g = h_even @ Wc + bc + bs ; only gc (cols 256:512) and go (512:768).
// cl = sig(gc)*c_even ; hl = sig(go)*tanh(cl)
// =====================================================================
__global__ void __launch_bounds__(THREADS, 2)
comb1_kernel(int src, const float* __restrict__ Wc,
             const float* __restrict__ bc, const float* __restrict__ bs,
             int Mout, float* __restrict__ root_out)
{
    const float* __restrict__ h_in = src ? g_hB : g_hA;
    const float* __restrict__ c_in = src ? g_cB : g_cA;
    float* __restrict__ hl_out = root_out ? root_out : g_hl;
    float* __restrict__ cl_out = root_out ? g_rc : g_cl;

    __shared__ float As[BK][AP];
    __shared__ float Bs[BK][BP2];

    const int tid = threadIdx.x;
    const int tx = tid & 15;
    const int ty = tid >> 4;
    const int m0 = blockIdx.x * BM;
    const int u0 = blockIdx.y * BU;

    ull acc[8][2];
#pragma unroll
    for (int r = 0; r < 8; r++) { acc[r][0] = 0ull; acc[r][1] = 0ull; }

    for (int k0 = 0; k0 < DH; k0 += BK) {
#pragma unroll
        for (int i = 0; i < 4; i++) {
            int idx = tid + i * THREADS;
            int m = idx >> 3;
            int kq = idx & 7;
            float4 v = make_float4(0.f, 0.f, 0.f, 0.f);
            if (m0 + m < Mout)
                v = *reinterpret_cast<const float4*>(
                    &h_in[(size_t)(2 * (m0 + m)) * DH + k0 + kq * 4]);
            As[kq * 4 + 0][m] = v.x;
            As[kq * 4 + 1][m] = v.y;
            As[kq * 4 + 2][m] = v.z;
            As[kq * 4 + 3][m] = v.w;
        }
        {
            int kk = tid >> 3;
#pragma unroll
            for (int i = 0; i < 2; i++) {
                int c4 = (tid & 7) + i * 8;
                int g = c4 >> 3;
                int u4 = c4 & 7;
                float4 w = *reinterpret_cast<const float4*>(
                    &Wc[(size_t)(k0 + kk) * 768 + 256 + g * 256 + u0 + u4 * 4]);
                *reinterpret_cast<float4*>(&Bs[kk][g * 32 + u4 * 4]) = w;
            }
        }
        __syncthreads();
#pragma unroll 8
        for (int kk = 0; kk < BK; kk++) {
            float4 a0 = *reinterpret_cast<const float4*>(&As[kk][ty * 8]);
            float4 a1 = *reinterpret_cast<const float4*>(&As[kk][ty * 8 + 4]);
            ull ap[8] = {pack2(a0.x), pack2(a0.y), pack2(a0.z), pack2(a0.w),
                         pack2(a1.x), pack2(a1.y), pack2(a1.z), pack2(a1.w)};
            ull b0 = *reinterpret_cast<const ull*>(&Bs[kk][tx * 2]);
            ull b1 = *reinterpret_cast<const ull*>(&Bs[kk][32 + tx * 2]);
#pragma unroll
            for (int r = 0; r < 8; r++) {
                ffma2(acc[r][0], ap[r], b0);
                ffma2(acc[r][1], ap[r], b1);
            }
        }
        __syncthreads();
    }

    const int u = u0 + tx * 2;
    const float2 bgc = make_float2(bc[256 + u] + bs[256 + u], bc[256 + u + 1] + bs[256 + u + 1]);
    const float2 bgo = make_float2(bc[512 + u] + bs[512 + u], bc[512 + u + 1] + bs[512 + u + 1]);
#pragma unroll
    for (int r = 0; r < 8; r++) {
        int row = m0 + ty * 8 + r;
        if (row < Mout) {
            float2 gc = unpack2(acc[r][0]); gc.x += bgc.x; gc.y += bgc.y;
            float2 go = unpack2(acc[r][1]); go.x += bgo.x; go.y += bgo.y;
            float2 cc = *reinterpret_cast<const float2*>(&c_in[(size_t)(2 * row) * DH + u]);
            float clx = sigf(gc.x) * cc.x;
            float cly = sigf(gc.y) * cc.y;
            float hlx = sigf(go.x) * tanhf(clx);
            float hly = sigf(go.y) * tanhf(cly);
            *reinterpret_cast<float2*>(&cl_out[(size_t)row * DH + u]) = make_float2(clx, cly);
            *reinterpret_cast<float2*>(&hl_out[(size_t)row * DH + u]) = make_float2(hlx, hly);
        }
    }
}

// =====================================================================
// Stage 2 per level: right child, sibling = stage-1 output.
// g = h_odd @ Wc + hl @ Ws + bc + bs  (K = 512 by concatenation)
// c' = sig(gc)*c_odd + sig(gs)*cl ; h' = sig(go)*tanh(c')
// =====================================================================
__global__ void __launch_bounds__(THREADS, 2)
comb2_kernel(int src, const float* __restrict__ Wc, const float* __restrict__ Ws,
             const float* __restrict__ bc, const float* __restrict__ bs, int Mout)
{
    const float* __restrict__ h_in = src ? g_hB : g_hA;
    const float* __restrict__ c_in = src ? g_cB : g_cA;
    float* __restrict__ h_out = src ? g_hA : g_hB;
    float* __restrict__ c_out = src ? g_cA : g_cB;

    __shared__ float As[BK][AP];
    __shared__ float Bs[BK][BP3];

    const int tid = threadIdx.x;
    const int tx = tid & 15;
    const int ty = tid >> 4;
    const int m0 = blockIdx.x * BM;
    const int u0 = blockIdx.y * BU;

    ull acc[8][3];
#pragma unroll
    for (int r = 0; r < 8; r++)
#pragma unroll
        for (int g = 0; g < 3; g++) acc[r][g] = 0ull;

    for (int k0 = 0; k0 < 2 * DH; k0 += BK) {
        const bool second = (k0 >= DH);
        const float* __restrict__ W = second ? Ws : Wc;
        const int kw = k0 & (DH - 1);
#pragma unroll
        for (int i = 0; i < 4; i++) {
            int idx = tid + i * THREADS;
            int m = idx >> 3;
            int kq = idx & 7;
            float4 v = make_float4(0.f, 0.f, 0.f, 0.f);
            if (m0 + m < Mout) {
                const float* src_row = second
                    ? &g_hl[(size_t)(m0 + m) * DH]
                    : &h_in[(size_t)(2 * (m0 + m) + 1) * DH];
                v = *reinterpret_cast<const float4*>(&src_row[kw + kq * 4]);
            }
            As[kq * 4 + 0][m] = v.x;
            As[kq * 4 + 1][m] = v.y;
            As[kq * 4 + 2][m] = v.z;
            As[kq * 4 + 3][m] = v.w;
        }
        {
            int kk = tid >> 3;
#pragma unroll
            for (int i = 0; i < 3; i++) {
                int c4 = (tid & 7) + i * 8;
                int g = c4 >> 3;
                int u4 = c4 & 7;
                float4 w = *reinterpret_cast<const float4*>(
                    &W[(size_t)(kw + kk) * 768 + g * 256 + u0 + u4 * 4]);
                *reinterpret_cast<float4*>(&Bs[kk][g * 32 + u4 * 4]) = w;
            }
        }
        __syncthreads();
#pragma unroll 8
        for (int kk = 0; kk < BK; kk++) {
            float4 a0 = *reinterpret_cast<const float4*>(&As[kk][ty * 8]);
            float4 a1 = *reinterpret_cast<const float4*>(&As[kk][ty * 8 + 4]);
            ull ap[8] = {pack2(a0.x), pack2(a0.y), pack2(a0.z), pack2(a0.w),
                         pack2(a1.x), pack2(a1.y), pack2(a1.z), pack2(a1.w)};
            ull b0 = *reinterpret_cast<const ull*>(&Bs[kk][tx * 2]);
            ull b1 = *reinterpret_cast<const ull*>(&Bs[kk][32 + tx * 2]);
            ull b2 = *reinterpret_cast<const ull*>(&Bs[kk][64 + tx * 2]);
#pragma unroll
            for (int r = 0; r < 8; r++) {
                ffma2(acc[r][0], ap[r], b0);
                ffma2(acc[r][1], ap[r], b1);
                ffma2(acc[r][2], ap[r], b2);
            }
        }
        __syncthreads();
    }

    const int u = u0 + tx * 2;
    const float2 bgs = make_float2(bc[u] + bs[u], bc[u + 1] + bs[u + 1]);
    const float2 bgc = make_float2(bc[256 + u] + bs[256 + u], bc[256 + u + 1] + bs[256 + u + 1]);
    const float2 bgo = make_float2(bc[512 + u] + bs[512 + u], bc[512 + u + 1] + bs[512 + u + 1]);
#pragma unroll
    for (int r = 0; r < 8; r++) {
        int row = m0 + ty * 8 + r;
        if (row < Mout) {
            float2 gs_ = unpack2(acc[r][0]); gs_.x += bgs.x; gs_.y += bgs.y;
            float2 gc  = unpack2(acc[r][1]); gc.x  += bgc.x; gc.y  += bgc.y;
            float2 go  = unpack2(acc[r][2]); go.x  += bgo.x; go.y  += bgo.y;
            float2 co = *reinterpret_cast<const float2*>(&c_in[(size_t)(2 * row + 1) * DH + u]);
            float2 cs = *reinterpret_cast<const float2*>(&g_cl[(size_t)row * DH + u]);
            float cnx = sigf(gc.x) * co.x + sigf(gs_.x) * cs.x;
            float cny = sigf(gc.y) * co.y + sigf(gs_.y) * cs.y;
            float hnx = sigf(go.x) * tanhf(cnx);
            float hny = sigf(go.y) * tanhf(cny);
            *reinterpret_cast<float2*>(&c_out[(size_t)row * DH + u]) = make_float2(cnx, cny);
            *reinterpret_cast<float2*>(&h_out[(size_t)row * DH + u]) = make_float2(hnx, hny);
        }
    }
}

// =====================================================================
extern "C" void kernel_launch(void* const* d_in, const int* in_sizes, int n_in,
                              void* d_out, int out_size)
{
    const int*   ids = (const int*)d_in[0];
    const float* emb = (const float*)d_in[1];
    const float* Wx  = (const float*)d_in[2];
    const float* bx  = (const float*)d_in[3];
    const float* Ws  = (const float*)d_in[4];
    const float* bs  = (const float*)d_in[5];
    const float* Wc  = (const float*)d_in[6];
    const float* bc  = (const float*)d_in[7];
    float* out = (float*)d_out;
    (void)in_sizes; (void)n_in; (void)out_size;

    leaf_kernel<<<dim3(NLEAF / BM, DH / BU), THREADS>>>(ids, emb, Wx, bx);

    int M = NLEAF;
    for (int l = 0; l < 14; l++) {
        int Mo = M >> 1;
        int src = l & 1;   // 0: read A (write B), 1: read B (write A)
        dim3 grid((Mo + BM - 1) / BM, DH / BU);
        comb1_kernel<<<grid, THREADS>>>(src, Wc, bc, bs, Mo, nullptr);
        comb2_kernel<<<grid, THREADS>>>(src, Wc, Ws, bc, bs, Mo);
        M = Mo;
    }
    // After 14 levels the single node sits in the A buffers (14 is even).
    comb1_kernel<<<dim3(1, DH / BU), THREADS>>>(0, Wc, bc, bs, 1, out);
}